// round 17
// baseline (speedup 1.0000x reference)
#include <cuda_runtime.h>
#include <cstdint>
#include <float.h>

// Sparsemax: each 256-thread block owns TWO rows with double-buffered TMA.
// Both row loads are issued up front; row1's load is in flight while row0 is
// computed, and row0's bulk store drains while row1 is computed -> the
// block's DRAM demand is continuous (fixes the 57% bursty duty cycle that
// R16's prefetch experiment diagnosed) with zero extra traffic.
//
// Per row: thresh = rowmax - 1 (tau >= thresh always) -> support C =
// {x > thresh}, |C| ~ 6 for Gaussian rows. Gather gated by per-thread pass-A
// max (exact). Exact Newton/Michelot on C, redundantly on every warp (no
// broadcast barrier). Guarded block-Michelot fallback keeps any input
// correct. Output computed into the smem buffer in place, drained by one
// cp.async.bulk store per row (engine-driven, waited only at block end).

#define COLS 8192
#define C4   (COLS / 4)
#define T    256
#define VPT  (C4 / T)             // 8 float4 per thread
#define CAP  512
#define ROW_BYTES (COLS * 4)

struct __align__(128) Smem {
    float buf[2][COLS];           // 2 x 32 KB row buffers
    unsigned long long mbar[2];
    float cand[CAP];
    float red[T / 32];
    float fb[2 * (T / 32)];
    float smax;
    float stau;
    int   cnt[2];
    int   sdone;
};

__device__ __forceinline__ uint32_t s2u(const void* p) {
    return (uint32_t)__cvta_generic_to_shared(p);
}
__device__ __forceinline__ void mbar_wait0(uint32_t a) {
    uint32_t done;
    asm volatile(
        "{\n\t.reg .pred p;\n\t"
        "mbarrier.try_wait.parity.acquire.cta.shared::cta.b64 p, [%1], 0;\n\t"
        "selp.b32 %0, 1, 0, p;\n\t}"
        : "=r"(done) : "r"(a) : "memory");
    if (!done) {
        asm volatile(
            "{\n\t.reg .pred P1;\n\t"
            "W_%=:\n\t"
            "mbarrier.try_wait.parity.acquire.cta.shared::cta.b64 P1, [%0], 0, 0x989680;\n\t"
            "@P1 bra.uni D_%=;\n\t"
            "bra.uni W_%=;\n\t"
            "D_%=:\n\t}"
            :: "r"(a) : "memory");
    }
}

__global__ __launch_bounds__(T)
void sparsemax_2row(const float* __restrict__ x, float* __restrict__ out, int rows)
{
    extern __shared__ __align__(128) unsigned char smem_raw[];
    Smem* S = reinterpret_cast<Smem*>(smem_raw);

    const int tid  = threadIdx.x;
    const int lane = tid & 31;
    const int wid  = tid >> 5;
    const long long row0 = 2LL * blockIdx.x;
    if (row0 >= rows) return;
    const int nrow = (row0 + 1 < rows) ? 2 : 1;

    if (tid == 0) {
        S->cnt[0] = 0; S->cnt[1] = 0;
#pragma unroll
        for (int r = 0; r < 2; ++r)
            asm volatile("mbarrier.init.shared.b64 [%0], 1;"
                         :: "r"(s2u(&S->mbar[r])) : "memory");
    }
    __syncthreads();

    // ---- issue BOTH TMA loads up front ----
    if (tid == 0) {
        for (int r = 0; r < nrow; ++r) {
            uint32_t mb = s2u(&S->mbar[r]);
            asm volatile("mbarrier.arrive.expect_tx.shared.b64 _, [%0], %1;"
                         :: "r"(mb), "r"((uint32_t)ROW_BYTES) : "memory");
            asm volatile(
                "cp.async.bulk.shared::cta.global.mbarrier::complete_tx::bytes [%0], [%1], %2, [%3];"
                :: "r"(s2u(S->buf[r])), "l"((const void*)(x + (row0 + r) * COLS)),
                   "r"((uint32_t)ROW_BYTES), "r"(mb) : "memory");
        }
    }

#pragma unroll 1
    for (int r = 0; r < nrow; ++r) {
        const long long row = row0 + r;
        mbar_wait0(s2u(&S->mbar[r]));
        float4* __restrict__ b4 = reinterpret_cast<float4*>(S->buf[r]);

        // ---- pass A: smem scan, per-thread max (4 independent chains) ----
        float m0 = -FLT_MAX, m1 = -FLT_MAX, m2 = -FLT_MAX, m3 = -FLT_MAX;
#pragma unroll
        for (int i = 0; i < VPT; ++i) {
            float4 v = b4[tid + i * T];
            m0 = fmaxf(m0, v.x);
            m1 = fmaxf(m1, v.y);
            m2 = fmaxf(m2, v.z);
            m3 = fmaxf(m3, v.w);
        }
        const float tmax = fmaxf(fmaxf(m0, m1), fmaxf(m2, m3));

        // ---- block max ----
        float m = tmax;
#pragma unroll
        for (int o = 16; o > 0; o >>= 1) m = fmaxf(m, __shfl_xor_sync(0xffffffffu, m, o));
        if (lane == 0) S->red[wid] = m;
        __syncthreads();
        if (wid == 0) {
            float t = (lane < T / 32) ? S->red[lane] : -FLT_MAX;
#pragma unroll
            for (int o = 4; o > 0; o >>= 1) t = fmaxf(t, __shfl_xor_sync(0xffffffffu, t, o));
            if (lane == 0) S->smax = t;
        }
        __syncthreads();
        const float thresh = S->smax - 1.0f;           // tau >= thresh always

        // ---- gather: only threads whose own max clears thresh re-scan ----
        if (tmax > thresh) {
#pragma unroll 1
            for (int i = 0; i < VPT; ++i) {
                float4 v = b4[tid + i * T];
                if (v.x > thresh) { int q = atomicAdd(&S->cnt[r], 1); if (q < CAP) S->cand[q] = v.x; }
                if (v.y > thresh) { int q = atomicAdd(&S->cnt[r], 1); if (q < CAP) S->cand[q] = v.y; }
                if (v.z > thresh) { int q = atomicAdd(&S->cnt[r], 1); if (q < CAP) S->cand[q] = v.z; }
                if (v.w > thresh) { int q = atomicAdd(&S->cnt[r], 1); if (q < CAP) S->cand[q] = v.w; }
            }
        }
        __syncthreads();
        const int cnt = S->cnt[r];

        float tau;
        if (cnt <= CAP) {
            // ---- exact Newton/Michelot, ALL warps redundantly ----
            float tt = thresh;
#pragma unroll 1
            for (int it = 0; it < 64; ++it) {
                float s = 0.0f, k = 0.0f;
                for (int i = lane; i < cnt; i += 32) {
                    float c = S->cand[i];
                    if (c > tt) { s += c; k += 1.0f; }
                }
#pragma unroll
                for (int o = 16; o > 0; o >>= 1) {
                    s += __shfl_xor_sync(0xffffffffu, s, o);
                    k += __shfl_xor_sync(0xffffffffu, k, o);
                }
                if (k < 0.5f) break;          // safety (cannot happen in theory)
                float nt = (s - 1.0f) / k;
                if (nt == tt) break;          // exact fixed point
                tt = nt;
            }
            tau = tt;
        } else {
            // ---- pathological fallback: block Michelot over smem row ----
            float tt = thresh;
#pragma unroll 1
            for (int it = 0; it < 64; ++it) {
                float s = 0.0f, k = 0.0f;
#pragma unroll 1
                for (int i = 0; i < VPT; ++i) {
                    float4 v = b4[tid + i * T];
                    if (v.x > tt) { s += v.x; k += 1.0f; }
                    if (v.y > tt) { s += v.y; k += 1.0f; }
                    if (v.z > tt) { s += v.z; k += 1.0f; }
                    if (v.w > tt) { s += v.w; k += 1.0f; }
                }
#pragma unroll
                for (int o = 16; o > 0; o >>= 1) {
                    s += __shfl_xor_sync(0xffffffffu, s, o);
                    k += __shfl_xor_sync(0xffffffffu, k, o);
                }
                if (lane == 0) { S->fb[2 * wid] = s; S->fb[2 * wid + 1] = k; }
                __syncthreads();
                if (tid == 0) {
                    float Sx = 0.0f, K = 0.0f;
                    for (int w = 0; w < T / 32; ++w) { Sx += S->fb[2 * w]; K += S->fb[2 * w + 1]; }
                    float nt = (K < 0.5f) ? tt : (Sx - 1.0f) / K;
                    S->sdone = (nt == tt) || (K < 0.5f);
                    S->stau  = nt;
                }
                __syncthreads();
                tt = S->stau;
                if (S->sdone) break;
            }
            tau = tt;
        }

        // ---- pass C: compute into smem in place (thread-private slots) ----
#pragma unroll
        for (int i = 0; i < VPT; ++i) {
            float4 v = b4[tid + i * T];
            float4 rr;
            rr.x = fmaxf(v.x - tau, 0.0f);
            rr.y = fmaxf(v.y - tau, 0.0f);
            rr.z = fmaxf(v.z - tau, 0.0f);
            rr.w = fmaxf(v.w - tau, 0.0f);
            b4[tid + i * T] = rr;
        }
        __syncthreads();

        // ---- bulk store this row (engine-driven; wait deferred to end) ----
        if (tid == 0) {
            asm volatile("fence.proxy.async.shared::cta;" ::: "memory");
            asm volatile(
                "cp.async.bulk.global.shared::cta.bulk_group [%0], [%1], %2;"
                :: "l"((void*)(out + row * COLS)), "r"(s2u(S->buf[r])),
                   "r"((uint32_t)ROW_BYTES) : "memory");
            asm volatile("cp.async.bulk.commit_group;" ::: "memory");
        }
        // no wait here: row r+1 uses the other buffer; store drains in
        // parallel with the next row's compute
    }

    // ---- drain all bulk stores before the CTA may release its smem ----
    if (tid == 0)
        asm volatile("cp.async.bulk.wait_group 0;" ::: "memory");
    __syncthreads();
}

extern "C" void kernel_launch(void* const* d_in, const int* in_sizes, int n_in,
                              void* d_out, int out_size)
{
    const float* x = (const float*)d_in[0];
    float* out     = (float*)d_out;
    const int rows = in_sizes[0] / COLS;
    cudaFuncSetAttribute(sparsemax_2row,
                         cudaFuncAttributeMaxDynamicSharedMemorySize,
                         (int)sizeof(Smem));
    const int grid = (rows + 1) / 2;
    sparsemax_2row<<<grid, T, sizeof(Smem)>>>(x, out, rows);
}